// round 4
// baseline (speedup 1.0000x reference)
#include <cuda_runtime.h>

#define FULL 0xffffffffu
#define WPB 4            // warps (rays) per block
#define HN 64
#define LVL 4
#define SN 64

__global__ __launch_bounds__(128)
void mr_kernel(const float* __restrict__ rays_o,
               const float* __restrict__ rays_d,
               const float* __restrict__ levels,
               const float* __restrict__ W1,
               const float* __restrict__ b1,
               const float* __restrict__ W2,
               const float* __restrict__ b2,
               float* __restrict__ out,
               int N, int do_mask)
{
    __shared__ float4 sPack[HN];        // (W1[0][j], W1[1][j], W1[2][j], b1[j])
    __shared__ float  sW2[HN];
    __shared__ float  slev[LVL];
    __shared__ float  sscal[WPB][SN];

    int tid = threadIdx.x;
    if (tid < HN) {
        sPack[tid] = make_float4(W1[tid], W1[HN + tid], W1[2*HN + tid], b1[tid]);
        sW2[tid] = W2[tid];
    }
    if (tid < LVL) slev[tid] = levels[tid];
    __syncthreads();

    float addc = b2[0] + 1.0f;          // b2 + R0

    int lane = tid & 31;
    int warp = tid >> 5;
    int ray  = blockIdx.x * WPB + warp;
    if (ray >= N) return;

    float ox = rays_o[ray*3+0], oy = rays_o[ray*3+1], oz = rays_o[ray*3+2];
    float dx = rays_d[ray*3+0], dy = rays_d[ray*3+1], dz = rays_d[ray*3+2];

    // sphere bounds
    float bq = ox*dx + oy*dy + oz*dz;
    float cq = ox*ox + oy*oy + oz*oz - 9.0f;
    float disc = bq*bq - cq;
    bool  hit = disc > 0.0f;
    float sq = sqrtf(hit ? disc : 1.0f);
    float dnear = fmaxf(-bq - sq, 0.0f);
    float dfar  = fminf(-bq + sq, 100.0f);
    bool  mask_bound = hit && (dnear < dfar);

    float* scal = sscal[warp];

    // ---------------- Phase A: sample evals (2 per lane) ----------------
    unsigned vm0 = 0u, vm1 = 0u;
    float minv = 3.402823466e38f;
    int   minj = 0;                      // argmin over scal[s], s in [1,63] -> pair j = s-1
    #pragma unroll
    for (int half = 0; half < 2; ++half) {
        int s = lane + half*32;
        float t = (float)s / 63.0f;
        float dd = dnear*(1.0f - t) + dfar*t;
        float x0 = fmaf(dx, dd, ox);
        float x1 = fmaf(dy, dd, oy);
        float x2 = fmaf(dz, dd, oz);
        float acc = 0.0f;
        #pragma unroll 8
        for (int j = 0; j < HN; ++j) {
            float4 w = sPack[j];
            float pre = fmaf(x0, w.x, fmaf(x1, w.y, fmaf(x2, w.z, w.w)));
            acc = fmaf(tanhf(pre), sW2[j], acc);
        }
        float nrm = sqrtf(x0*x0 + x1*x1 + x2*x2);
        float sv = acc + addc - nrm;
        bool valid = nrm < 3.0f;
        scal[s] = sv;
        unsigned bal = __ballot_sync(FULL, valid);
        if (half == 0) vm0 = bal; else vm1 = bal;
        if (s >= 1 && sv < minv) { minv = sv; minj = s - 1; }
    }
    __syncwarp();

    // warp-reduce argmin (first occurrence on ties -> smaller index)
    #pragma unroll
    for (int off = 16; off >= 1; off >>= 1) {
        float ov = __shfl_xor_sync(FULL, minv, off);
        int   oj = __shfl_xor_sync(FULL, minj, off);
        if (ov < minv || (ov == minv && oj < minj)) { minv = ov; minj = oj; }
    }

    // ---------------- Phase B: interval search, 8 lanes per level ----------------
    int   mylev = lane & 3;
    int   grp   = lane >> 2;
    float lval  = slev[mylev];
    float brank = -3.402823466e38f;
    int   bj    = 63;
    int   anyi  = 0;
    #pragma unroll
    for (int k = 0; k < 8; ++k) {
        int j = grp*8 + k;
        if (j < 63) {
            float sf = scal[j], sb = scal[j+1];
            float diff = lval - sb;
            float sgn = (diff > 0.0f) ? 1.0f : ((diff < 0.0f) ? -1.0f : 0.0f);
            float rank = sgn * (float)(63 - j);
            if (rank > brank) { brank = rank; bj = j; }   // ascending j -> first max kept
            unsigned wv  = (j  < 32) ? vm0 : vm1;
            unsigned wv1 = (j+1 < 32) ? vm0 : vm1;
            bool vj  = (wv  >> (j & 31)) & 1u;
            bool vj1 = (wv1 >> ((j+1) & 31)) & 1u;
            if ((sf >= lval) && (lval >= sb) && vj && vj1) anyi = 1;
        }
    }
    // reduce across the 8 lanes sharing a level (xor 4,8,16 keeps lane&3 fixed)
    #pragma unroll
    for (int off = 4; off <= 16; off <<= 1) {
        float orank = __shfl_xor_sync(FULL, brank, off);
        int   obj   = __shfl_xor_sync(FULL, bj, off);
        int   oany  = __shfl_xor_sync(FULL, anyi, off);
        anyi |= oany;
        if (orank > brank || (orank == brank && obj < bj)) { brank = orank; bj = obj; }
    }
    int idxsel = anyi ? bj : minj;

    // ---------------- Phase C: secant (warp-collective evals), per level ----------------
    float dint[LVL];
    int   mint[LVL];
    #pragma unroll
    for (int lev = 0; lev < LVL; ++lev) {
        int   idx = __shfl_sync(FULL, idxsel, lev);   // lane 'lev' holds level 'lev'
        float lv  = slev[lev];
        float tF = (float)idx / 63.0f;
        float tB = (float)(idx+1) / 63.0f;
        float d_front = dnear*(1.0f - tF) + dfar*tF;
        float d_back  = dnear*(1.0f - tB) + dfar*tB;
        float s_front = scal[idx], s_back = scal[idx+1];
        bool  m_int = (s_front >= lv) && (lv >= s_back);
        float sdiff = s_front - s_back;
        bool  mvd = fabsf(sdiff) > 1e-4f;
        bool  m_sec = m_int && mvd;
        float d_sec = ((lv - s_back)*d_front + (s_front - lv)*d_back) / (mvd ? sdiff : 1.0f);
        float d_init = m_sec ? d_sec : d_back;

        float dfs = d_front, dbs = d_back, sfs = s_front, sbs = s_back, dcur = d_init;
        #pragma unroll
        for (int it = 0; it < 4; ++it) {
            float x0 = fmaf(dx, dcur, ox);
            float x1 = fmaf(dy, dcur, oy);
            float x2 = fmaf(dz, dcur, oz);
            float4 wA = sPack[lane];
            float4 wB = sPack[lane + 32];
            float preA = fmaf(x0, wA.x, fmaf(x1, wA.y, fmaf(x2, wA.z, wA.w)));
            float preB = fmaf(x0, wB.x, fmaf(x1, wB.y, fmaf(x2, wB.z, wB.w)));
            float part = tanhf(preA)*sW2[lane] + tanhf(preB)*sW2[lane + 32];
            #pragma unroll
            for (int off = 16; off >= 1; off >>= 1)
                part += __shfl_xor_sync(FULL, part, off);   // identical on all lanes
            float nrm = sqrtf(x0*x0 + x1*x1 + x2*x2);
            float s_mid = part + addc - nrm;
            bool mv = nrm < 3.0f;
            bool upf = (s_mid > lv) && mv;
            bool upb = (s_mid < lv) && mv;
            if (upf) { dfs = dcur; sfs = s_mid; }
            if (upb) { dbs = dcur; sbs = s_mid; }
            float sd = sfs - sbs;
            bool ok = fabsf(sd) > 1e-4f;
            float dn = ((lv - sbs)*dfs + (sfs - lv)*dbs) / (ok ? sd : 1.0f);
            dcur = ok ? dn : dcur;
        }
        dint[lev] = m_sec ? dcur : d_init;
        mint[lev] = m_int ? 1 : 0;
    }

    // ---------------- stable ascending sort of 4 (adjacent swaps, strict <) ----------------
    float d0 = dint[0], d1 = dint[1], d2 = dint[2], d3 = dint[3];
    int   m0 = mint[0], m1 = mint[1], m2 = mint[2], m3 = mint[3];
    #define CSW(da,ma,db,mb) do { if ((db) < (da)) { float _t=(da); (da)=(db); (db)=_t; int _m=(ma); (ma)=(mb); (mb)=_m; } } while(0)
    CSW(d0,m0,d1,m1); CSW(d1,m1,d2,m2); CSW(d2,m2,d3,m3);
    CSW(d0,m0,d1,m1); CSW(d1,m1,d2,m2);
    CSW(d0,m0,d1,m1);
    #undef CSW

    if (lane == 0) {
        float4 dv = mask_bound ? make_float4(d0, d1, d2, d3)
                               : make_float4(0.f, 0.f, 0.f, 0.f);
        *reinterpret_cast<float4*>(out + (size_t)ray*4) = dv;
        if (do_mask) {
            float4 mv4 = mask_bound ? make_float4((float)m0, (float)m1, (float)m2, (float)m3)
                                    : make_float4(0.f, 0.f, 0.f, 0.f);
            *reinterpret_cast<float4*>(out + (size_t)N*4 + (size_t)ray*4) = mv4;
        }
    }
}

extern "C" void kernel_launch(void* const* d_in, const int* in_sizes, int n_in,
                              void* d_out, int out_size) {
    const float* rays_o = (const float*)d_in[0];
    const float* rays_d = (const float*)d_in[1];
    const float* levels = (const float*)d_in[2];
    const float* W1     = (const float*)d_in[3];
    const float* b1     = (const float*)d_in[4];
    const float* W2     = (const float*)d_in[5];
    const float* b2     = (const float*)d_in[6];
    int N = in_sizes[0] / 3;
    int do_mask = (out_size >= 2 * N * LVL) ? 1 : 0;
    int blocks = (N + WPB - 1) / WPB;
    mr_kernel<<<blocks, 128>>>(rays_o, rays_d, levels, W1, b1, W2, b2,
                               (float*)d_out, N, do_mask);
}

// round 5
// speedup vs baseline: 1.0016x; 1.0016x over previous
#include <cuda_runtime.h>

#define FULL 0xffffffffu
#define WPB 4            // warps (rays) per block
#define HN 64
#define LVL 4
#define SN 64

__global__ __launch_bounds__(128)
void mr_kernel(const float* __restrict__ rays_o,
               const float* __restrict__ rays_d,
               const float* __restrict__ levels,
               const float* __restrict__ W1,
               const float* __restrict__ b1,
               const float* __restrict__ W2,
               const float* __restrict__ b2,
               float* __restrict__ out,
               int N, int do_mask)
{
    __shared__ float4 sPack[HN];        // (W1[0][j], W1[1][j], W1[2][j], b1[j])
    __shared__ float  sW2[HN];
    __shared__ float  slev[LVL];
    __shared__ float  sscal[WPB][SN];

    int tid = threadIdx.x;
    if (tid < HN) {
        sPack[tid] = make_float4(W1[tid], W1[HN + tid], W1[2*HN + tid], b1[tid]);
        sW2[tid] = W2[tid];
    }
    if (tid < LVL) slev[tid] = levels[tid];
    __syncthreads();

    float addc = b2[0] + 1.0f;          // b2 + R0

    int lane = tid & 31;
    int warp = tid >> 5;
    int ray  = blockIdx.x * WPB + warp;
    if (ray >= N) return;

    float ox = rays_o[ray*3+0], oy = rays_o[ray*3+1], oz = rays_o[ray*3+2];
    float dx = rays_d[ray*3+0], dy = rays_d[ray*3+1], dz = rays_d[ray*3+2];

    // sphere bounds
    float bq = ox*dx + oy*dy + oz*dz;
    float cq = ox*ox + oy*oy + oz*oz - 9.0f;
    float disc = bq*bq - cq;
    bool  hit = disc > 0.0f;
    float sq = sqrtf(hit ? disc : 1.0f);
    float dnear = fmaxf(-bq - sq, 0.0f);
    float dfar  = fminf(-bq + sq, 100.0f);
    bool  mask_bound = hit && (dnear < dfar);

    float* scal = sscal[warp];

    // ---------------- Phase A: sample evals (2 per lane) ----------------
    unsigned vm0 = 0u, vm1 = 0u;
    float minv = 3.402823466e38f;
    int   minj = 0;                      // argmin over scal[s], s in [1,63] -> pair j = s-1
    #pragma unroll
    for (int half = 0; half < 2; ++half) {
        int s = lane + half*32;
        float t = (float)s / 63.0f;
        float dd = dnear*(1.0f - t) + dfar*t;
        float x0 = fmaf(dx, dd, ox);
        float x1 = fmaf(dy, dd, oy);
        float x2 = fmaf(dz, dd, oz);
        float acc = 0.0f;
        #pragma unroll 8
        for (int j = 0; j < HN; ++j) {
            float4 w = sPack[j];
            float pre = fmaf(x0, w.x, fmaf(x1, w.y, fmaf(x2, w.z, w.w)));
            acc = fmaf(tanhf(pre), sW2[j], acc);
        }
        float nrm = sqrtf(x0*x0 + x1*x1 + x2*x2);
        float sv = acc + addc - nrm;
        bool valid = nrm < 3.0f;
        scal[s] = sv;
        unsigned bal = __ballot_sync(FULL, valid);
        if (half == 0) vm0 = bal; else vm1 = bal;
        if (s >= 1 && sv < minv) { minv = sv; minj = s - 1; }
    }
    __syncwarp();

    // warp-reduce argmin (first occurrence on ties -> smaller index)
    #pragma unroll
    for (int off = 16; off >= 1; off >>= 1) {
        float ov = __shfl_xor_sync(FULL, minv, off);
        int   oj = __shfl_xor_sync(FULL, minj, off);
        if (ov < minv || (ov == minv && oj < minj)) { minv = ov; minj = oj; }
    }

    // ---------------- Phase B: interval search, 8 lanes per level ----------------
    int   mylev = lane & 3;
    int   grp   = lane >> 2;
    float lval  = slev[mylev];
    float brank = -3.402823466e38f;
    int   bj    = 63;
    int   anyi  = 0;
    #pragma unroll
    for (int k = 0; k < 8; ++k) {
        int j = grp*8 + k;
        if (j < 63) {
            float sf = scal[j], sb = scal[j+1];
            float diff = lval - sb;
            float sgn = (diff > 0.0f) ? 1.0f : ((diff < 0.0f) ? -1.0f : 0.0f);
            float rank = sgn * (float)(63 - j);
            if (rank > brank) { brank = rank; bj = j; }   // ascending j -> first max kept
            unsigned wv  = (j  < 32) ? vm0 : vm1;
            unsigned wv1 = (j+1 < 32) ? vm0 : vm1;
            bool vj  = (wv  >> (j & 31)) & 1u;
            bool vj1 = (wv1 >> ((j+1) & 31)) & 1u;
            if ((sf >= lval) && (lval >= sb) && vj && vj1) anyi = 1;
        }
    }
    // reduce across the 8 lanes sharing a level (xor 4,8,16 keeps lane&3 fixed)
    #pragma unroll
    for (int off = 4; off <= 16; off <<= 1) {
        float orank = __shfl_xor_sync(FULL, brank, off);
        int   obj   = __shfl_xor_sync(FULL, bj, off);
        int   oany  = __shfl_xor_sync(FULL, anyi, off);
        anyi |= oany;
        if (orank > brank || (orank == brank && obj < bj)) { brank = orank; bj = obj; }
    }
    int idxsel = anyi ? bj : minj;

    // ---------------- Phase C: secant (warp-collective evals), per level ----------------
    float dint[LVL];
    int   mint[LVL];
    #pragma unroll
    for (int lev = 0; lev < LVL; ++lev) {
        int   idx = __shfl_sync(FULL, idxsel, lev);   // lane 'lev' holds level 'lev'
        float lv  = slev[lev];
        float tF = (float)idx / 63.0f;
        float tB = (float)(idx+1) / 63.0f;
        float d_front = dnear*(1.0f - tF) + dfar*tF;
        float d_back  = dnear*(1.0f - tB) + dfar*tB;
        float s_front = scal[idx], s_back = scal[idx+1];
        bool  m_int = (s_front >= lv) && (lv >= s_back);
        float sdiff = s_front - s_back;
        bool  mvd = fabsf(sdiff) > 1e-4f;
        bool  m_sec = m_int && mvd;
        float d_sec = ((lv - s_back)*d_front + (s_front - lv)*d_back) / (mvd ? sdiff : 1.0f);
        float d_init = m_sec ? d_sec : d_back;

        float dfs = d_front, dbs = d_back, sfs = s_front, sbs = s_back, dcur = d_init;
        #pragma unroll
        for (int it = 0; it < 4; ++it) {
            float x0 = fmaf(dx, dcur, ox);
            float x1 = fmaf(dy, dcur, oy);
            float x2 = fmaf(dz, dcur, oz);
            float4 wA = sPack[lane];
            float4 wB = sPack[lane + 32];
            float preA = fmaf(x0, wA.x, fmaf(x1, wA.y, fmaf(x2, wA.z, wA.w)));
            float preB = fmaf(x0, wB.x, fmaf(x1, wB.y, fmaf(x2, wB.z, wB.w)));
            float part = tanhf(preA)*sW2[lane] + tanhf(preB)*sW2[lane + 32];
            #pragma unroll
            for (int off = 16; off >= 1; off >>= 1)
                part += __shfl_xor_sync(FULL, part, off);   // identical on all lanes
            float nrm = sqrtf(x0*x0 + x1*x1 + x2*x2);
            float s_mid = part + addc - nrm;
            bool mv = nrm < 3.0f;
            bool upf = (s_mid > lv) && mv;
            bool upb = (s_mid < lv) && mv;
            if (upf) { dfs = dcur; sfs = s_mid; }
            if (upb) { dbs = dcur; sbs = s_mid; }
            float sd = sfs - sbs;
            bool ok = fabsf(sd) > 1e-4f;
            float dn = ((lv - sbs)*dfs + (sfs - lv)*dbs) / (ok ? sd : 1.0f);
            dcur = ok ? dn : dcur;
        }
        dint[lev] = m_sec ? dcur : d_init;
        mint[lev] = m_int ? 1 : 0;
    }

    // ---------------- stable ascending sort of 4 (adjacent swaps, strict <) ----------------
    float d0 = dint[0], d1 = dint[1], d2 = dint[2], d3 = dint[3];
    int   m0 = mint[0], m1 = mint[1], m2 = mint[2], m3 = mint[3];
    #define CSW(da,ma,db,mb) do { if ((db) < (da)) { float _t=(da); (da)=(db); (db)=_t; int _m=(ma); (ma)=(mb); (mb)=_m; } } while(0)
    CSW(d0,m0,d1,m1); CSW(d1,m1,d2,m2); CSW(d2,m2,d3,m3);
    CSW(d0,m0,d1,m1); CSW(d1,m1,d2,m2);
    CSW(d0,m0,d1,m1);
    #undef CSW

    if (lane == 0) {
        float4 dv = mask_bound ? make_float4(d0, d1, d2, d3)
                               : make_float4(0.f, 0.f, 0.f, 0.f);
        *reinterpret_cast<float4*>(out + (size_t)ray*4) = dv;
        if (do_mask) {
            float4 mv4 = mask_bound ? make_float4((float)m0, (float)m1, (float)m2, (float)m3)
                                    : make_float4(0.f, 0.f, 0.f, 0.f);
            *reinterpret_cast<float4*>(out + (size_t)N*4 + (size_t)ray*4) = mv4;
        }
    }
}

extern "C" void kernel_launch(void* const* d_in, const int* in_sizes, int n_in,
                              void* d_out, int out_size) {
    const float* rays_o = (const float*)d_in[0];
    const float* rays_d = (const float*)d_in[1];
    const float* levels = (const float*)d_in[2];
    const float* W1     = (const float*)d_in[3];
    const float* b1     = (const float*)d_in[4];
    const float* W2     = (const float*)d_in[5];
    const float* b2     = (const float*)d_in[6];
    int N = in_sizes[0] / 3;
    int do_mask = (out_size >= 2 * N * LVL) ? 1 : 0;
    int blocks = (N + WPB - 1) / WPB;
    mr_kernel<<<blocks, 128>>>(rays_o, rays_d, levels, W1, b1, W2, b2,
                               (float*)d_out, N, do_mask);
}

// round 6
// speedup vs baseline: 1.1714x; 1.1695x over previous
#include <cuda_runtime.h>

#define FULL 0xffffffffu
#define WPB 4            // warps (rays) per block
#define HN 64
#define LVL 4
#define SN 64

__device__ __forceinline__ float fast_ex2(float x) {
    float y; asm("ex2.approx.f32 %0, %1;" : "=f"(y) : "f"(x)); return y;
}
__device__ __forceinline__ float fast_rcp(float x) {
    float y; asm("rcp.approx.f32 %0, %1;" : "=f"(y) : "f"(x)); return y;
}
__device__ __forceinline__ float fast_sqrt(float x) {
    float y; asm("sqrt.approx.f32 %0, %1;" : "=f"(y) : "f"(x)); return y;
}

// tanh(p/K) where p is already scaled by K = 2*log2(e):
//   tanh = 1 - 2/(1 + exp2(p))
__device__ __forceinline__ float tanh_r(float p) {   // returns r = 1/(1+exp2(p))
    return fast_rcp(1.0f + fast_ex2(p));
}

__global__ __launch_bounds__(128)
void mr_kernel(const float* __restrict__ rays_o,
               const float* __restrict__ rays_d,
               const float* __restrict__ levels,
               const float* __restrict__ W1,
               const float* __restrict__ b1,
               const float* __restrict__ W2,
               const float* __restrict__ b2,
               float* __restrict__ out,
               int N, int do_mask)
{
    __shared__ float4 sPack[HN];        // K*(W1[0][j], W1[1][j], W1[2][j], b1[j])
    __shared__ float  sW2m2[HN];        // -2 * W2[j]
    __shared__ float  slev[LVL];
    __shared__ float  sw2sum;           // sum_j W2[j]
    __shared__ float  sscal[WPB][SN];

    const float K = 2.8853900817779268f;   // 2*log2(e)

    int tid = threadIdx.x;
    if (tid < HN) {
        sPack[tid] = make_float4(K*W1[tid], K*W1[HN + tid], K*W1[2*HN + tid], K*b1[tid]);
        sW2m2[tid] = -2.0f * W2[tid];
    }
    if (tid < LVL) slev[tid] = levels[tid];
    if (tid == 0) {
        float s = 0.0f;
        #pragma unroll 8
        for (int j = 0; j < HN; ++j) s += W2[j];
        sw2sum = s;
    }
    __syncthreads();

    float addc  = b2[0] + 1.0f;          // b2 + R0
    float cbase = addc + sw2sum;         // constant part of s after the -2*w2*r fold

    int lane = tid & 31;
    int warp = tid >> 5;
    int ray  = blockIdx.x * WPB + warp;
    if (ray >= N) return;

    float ox = rays_o[ray*3+0], oy = rays_o[ray*3+1], oz = rays_o[ray*3+2];
    float dx = rays_d[ray*3+0], dy = rays_d[ray*3+1], dz = rays_d[ray*3+2];

    // sphere bounds
    float bq = ox*dx + oy*dy + oz*dz;
    float cq = ox*ox + oy*oy + oz*oz - 9.0f;
    float disc = bq*bq - cq;
    bool  hit = disc > 0.0f;
    float sq = sqrtf(hit ? disc : 1.0f);
    float dnear = fmaxf(-bq - sq, 0.0f);
    float dfar  = fminf(-bq + sq, 100.0f);
    bool  mask_bound = hit && (dnear < dfar);

    float* scal = sscal[warp];

    // ---------------- Phase A: sample evals (2 per lane) ----------------
    unsigned vm0 = 0u, vm1 = 0u;
    float minv = 3.402823466e38f;
    int   minj = 0;                      // argmin over scal[s], s in [1,63] -> pair j = s-1
    #pragma unroll
    for (int half = 0; half < 2; ++half) {
        int s = lane + half*32;
        float t = (float)s / 63.0f;
        float dd = dnear*(1.0f - t) + dfar*t;
        float x0 = fmaf(dx, dd, ox);
        float x1 = fmaf(dy, dd, oy);
        float x2 = fmaf(dz, dd, oz);
        float acc = 0.0f;
        #pragma unroll 16
        for (int j = 0; j < HN; ++j) {
            float4 w = sPack[j];
            float pre = fmaf(x0, w.x, fmaf(x1, w.y, fmaf(x2, w.z, w.w)));
            float r = tanh_r(pre);
            acc = fmaf(sW2m2[j], r, acc);
        }
        float nrm = fast_sqrt(x0*x0 + x1*x1 + x2*x2);
        float sv = acc + cbase - nrm;
        bool valid = nrm < 3.0f;
        scal[s] = sv;
        unsigned bal = __ballot_sync(FULL, valid);
        if (half == 0) vm0 = bal; else vm1 = bal;
        if (s >= 1 && sv < minv) { minv = sv; minj = s - 1; }
    }
    __syncwarp();

    // warp-reduce argmin (first occurrence on ties -> smaller index)
    #pragma unroll
    for (int off = 16; off >= 1; off >>= 1) {
        float ov = __shfl_xor_sync(FULL, minv, off);
        int   oj = __shfl_xor_sync(FULL, minj, off);
        if (ov < minv || (ov == minv && oj < minj)) { minv = ov; minj = oj; }
    }

    // ---------------- Phase B: interval search, 8 lanes per level ----------------
    int   mylev = lane & 3;
    int   grp   = lane >> 2;
    float lval  = slev[mylev];
    float brank = -3.402823466e38f;
    int   bj    = 63;
    int   anyi  = 0;
    #pragma unroll
    for (int k = 0; k < 8; ++k) {
        int j = grp*8 + k;
        if (j < 63) {
            float sf = scal[j], sb = scal[j+1];
            float diff = lval - sb;
            float sgn = (diff > 0.0f) ? 1.0f : ((diff < 0.0f) ? -1.0f : 0.0f);
            float rank = sgn * (float)(63 - j);
            if (rank > brank) { brank = rank; bj = j; }   // ascending j -> first max kept
            unsigned wv  = (j  < 32) ? vm0 : vm1;
            unsigned wv1 = (j+1 < 32) ? vm0 : vm1;
            bool vj  = (wv  >> (j & 31)) & 1u;
            bool vj1 = (wv1 >> ((j+1) & 31)) & 1u;
            if ((sf >= lval) && (lval >= sb) && vj && vj1) anyi = 1;
        }
    }
    // reduce across the 8 lanes sharing a level (xor 4,8,16 keeps lane&3 fixed)
    #pragma unroll
    for (int off = 4; off <= 16; off <<= 1) {
        float orank = __shfl_xor_sync(FULL, brank, off);
        int   obj   = __shfl_xor_sync(FULL, bj, off);
        int   oany  = __shfl_xor_sync(FULL, anyi, off);
        anyi |= oany;
        if (orank > brank || (orank == brank && obj < bj)) { brank = orank; bj = obj; }
    }
    int idxsel = anyi ? bj : minj;

    // ---------------- Phase C: secant (warp-collective evals), per level ----------------
    float4 wA = sPack[lane];
    float4 wB = sPack[lane + 32];
    float  m2A = sW2m2[lane];
    float  m2B = sW2m2[lane + 32];
    float  w2pair = -0.5f * (m2A + m2B);   // w2[lane] + w2[lane+32]; warp-sum -> sw2sum

    float dint[LVL];
    int   mint[LVL];
    #pragma unroll
    for (int lev = 0; lev < LVL; ++lev) {
        int   idx = __shfl_sync(FULL, idxsel, lev);   // lane 'lev' holds level 'lev'
        float lv  = slev[lev];
        float tF = (float)idx / 63.0f;
        float tB = (float)(idx+1) / 63.0f;
        float d_front = dnear*(1.0f - tF) + dfar*tF;
        float d_back  = dnear*(1.0f - tB) + dfar*tB;
        float s_front = scal[idx], s_back = scal[idx+1];
        bool  m_int = (s_front >= lv) && (lv >= s_back);
        float sdiff = s_front - s_back;
        bool  mvd = fabsf(sdiff) > 1e-4f;
        bool  m_sec = m_int && mvd;
        float d_sec = ((lv - s_back)*d_front + (s_front - lv)*d_back) / (mvd ? sdiff : 1.0f);
        float d_init = m_sec ? d_sec : d_back;

        float dfs = d_front, dbs = d_back, sfs = s_front, sbs = s_back, dcur = d_init;
        #pragma unroll
        for (int it = 0; it < 4; ++it) {
            float x0 = fmaf(dx, dcur, ox);
            float x1 = fmaf(dy, dcur, oy);
            float x2 = fmaf(dz, dcur, oz);
            float preA = fmaf(x0, wA.x, fmaf(x1, wA.y, fmaf(x2, wA.z, wA.w)));
            float preB = fmaf(x0, wB.x, fmaf(x1, wB.y, fmaf(x2, wB.z, wB.w)));
            float rA = tanh_r(preA);
            float rB = tanh_r(preB);
            // w2A*tanhA + w2B*tanhB = (w2A+w2B) + m2A*rA + m2B*rB
            float part = fmaf(m2A, rA, fmaf(m2B, rB, w2pair));
            #pragma unroll
            for (int off = 16; off >= 1; off >>= 1)
                part += __shfl_xor_sync(FULL, part, off);   // identical on all lanes
            float nrm = fast_sqrt(x0*x0 + x1*x1 + x2*x2);
            float s_mid = part + addc - nrm;                // part sums to sw2sum + acc terms
            bool mv = nrm < 3.0f;
            bool upf = (s_mid > lv) && mv;
            bool upb = (s_mid < lv) && mv;
            if (upf) { dfs = dcur; sfs = s_mid; }
            if (upb) { dbs = dcur; sbs = s_mid; }
            float sd = sfs - sbs;
            bool ok = fabsf(sd) > 1e-4f;
            float dn = ((lv - sbs)*dfs + (sfs - lv)*dbs) / (ok ? sd : 1.0f);
            dcur = ok ? dn : dcur;
        }
        dint[lev] = m_sec ? dcur : d_init;
        mint[lev] = m_int ? 1 : 0;
    }

    // ---------------- stable ascending sort of 4 (adjacent swaps, strict <) ----------------
    float d0 = dint[0], d1 = dint[1], d2 = dint[2], d3 = dint[3];
    int   m0 = mint[0], m1 = mint[1], m2 = mint[2], m3 = mint[3];
    #define CSW(da,ma,db,mb) do { if ((db) < (da)) { float _t=(da); (da)=(db); (db)=_t; int _m=(ma); (ma)=(mb); (mb)=_m; } } while(0)
    CSW(d0,m0,d1,m1); CSW(d1,m1,d2,m2); CSW(d2,m2,d3,m3);
    CSW(d0,m0,d1,m1); CSW(d1,m1,d2,m2);
    CSW(d0,m0,d1,m1);
    #undef CSW

    if (lane == 0) {
        float4 dv = mask_bound ? make_float4(d0, d1, d2, d3)
                               : make_float4(0.f, 0.f, 0.f, 0.f);
        *reinterpret_cast<float4*>(out + (size_t)ray*4) = dv;
        if (do_mask) {
            float4 mv4 = mask_bound ? make_float4((float)m0, (float)m1, (float)m2, (float)m3)
                                    : make_float4(0.f, 0.f, 0.f, 0.f);
            *reinterpret_cast<float4*>(out + (size_t)N*4 + (size_t)ray*4) = mv4;
        }
    }
}

extern "C" void kernel_launch(void* const* d_in, const int* in_sizes, int n_in,
                              void* d_out, int out_size) {
    const float* rays_o = (const float*)d_in[0];
    const float* rays_d = (const float*)d_in[1];
    const float* levels = (const float*)d_in[2];
    const float* W1     = (const float*)d_in[3];
    const float* b1     = (const float*)d_in[4];
    const float* W2     = (const float*)d_in[5];
    const float* b2     = (const float*)d_in[6];
    int N = in_sizes[0] / 3;
    int do_mask = (out_size >= 2 * N * LVL) ? 1 : 0;
    int blocks = (N + WPB - 1) / WPB;
    mr_kernel<<<blocks, 128>>>(rays_o, rays_d, levels, W1, b1, W2, b2,
                               (float*)d_out, N, do_mask);
}

// round 7
// speedup vs baseline: 1.2600x; 1.0757x over previous
#include <cuda_runtime.h>

#define FULL 0xffffffffu
#define WPB 4            // warps (rays) per block
#define HN 64
#define NPAIR 32
#define LVL 4
#define SN 64

__device__ __forceinline__ float fast_ex2(float x) {
    float y; asm("ex2.approx.f32 %0, %1;" : "=f"(y) : "f"(x)); return y;
}
__device__ __forceinline__ float fast_rcp(float x) {
    float y; asm("rcp.approx.f32 %0, %1;" : "=f"(y) : "f"(x)); return y;
}
__device__ __forceinline__ float fast_sqrt(float x) {
    float y; asm("sqrt.approx.f32 %0, %1;" : "=f"(y) : "f"(x)); return y;
}
__device__ __forceinline__ unsigned long long pk2(float lo, float hi) {
    unsigned long long r; asm("mov.b64 %0, {%1, %2};" : "=l"(r) : "f"(lo), "f"(hi)); return r;
}
__device__ __forceinline__ void upk2(unsigned long long v, float& lo, float& hi) {
    asm("mov.b64 {%0, %1}, %2;" : "=f"(lo), "=f"(hi) : "l"(v));
}
__device__ __forceinline__ unsigned long long fma2(unsigned long long a,
                                                   unsigned long long b,
                                                   unsigned long long c) {
    unsigned long long d;
    asm("fma.rn.f32x2 %0, %1, %2, %3;" : "=l"(d) : "l"(a), "l"(b), "l"(c));
    return d;
}

__global__ __launch_bounds__(128)
void mr_kernel(const float* __restrict__ rays_o,
               const float* __restrict__ rays_d,
               const float* __restrict__ levels,
               const float* __restrict__ W1,
               const float* __restrict__ b1,
               const float* __restrict__ W2,
               const float* __restrict__ b2,
               float* __restrict__ out,
               int N, int do_mask)
{
    // pair-interleaved weights, scaled by K = 2*log2(e):
    //   sPA[p] = (Kwx_j, Kwx_j1, Kwy_j, Kwy_j1)
    //   sPB[p] = (Kwz_j, Kwz_j1, Kb1_j, Kb1_j1)
    //   sM2[p] = (-2w2_j, -2w2_j1)
    __shared__ float4 sPA[NPAIR];
    __shared__ float4 sPB[NPAIR];
    __shared__ float2 sM2[NPAIR];
    __shared__ float  slev[LVL];
    __shared__ float  sw2sum;
    __shared__ float  sscal[WPB][SN];

    const float K = 2.8853900817779268f;   // 2*log2(e)

    int tid = threadIdx.x;
    if (tid < NPAIR) {
        int j = 2*tid, j1 = j + 1;
        sPA[tid] = make_float4(K*W1[j], K*W1[j1], K*W1[HN + j], K*W1[HN + j1]);
        sPB[tid] = make_float4(K*W1[2*HN + j], K*W1[2*HN + j1], K*b1[j], K*b1[j1]);
        sM2[tid] = make_float2(-2.0f*W2[j], -2.0f*W2[j1]);
    }
    if (tid < LVL) slev[tid] = levels[tid];
    if (tid == 0) {
        float s = 0.0f;
        #pragma unroll 8
        for (int j = 0; j < HN; ++j) s += W2[j];
        sw2sum = s;
    }
    __syncthreads();

    float addc  = b2[0] + 1.0f;          // b2 + R0
    float cbase = addc + sw2sum;         // constant after the -2*w2*r fold

    int lane = tid & 31;
    int warp = tid >> 5;
    int ray  = blockIdx.x * WPB + warp;
    if (ray >= N) return;

    float ox = rays_o[ray*3+0], oy = rays_o[ray*3+1], oz = rays_o[ray*3+2];
    float dx = rays_d[ray*3+0], dy = rays_d[ray*3+1], dz = rays_d[ray*3+2];

    // sphere bounds
    float bq = ox*dx + oy*dy + oz*dz;
    float cq = ox*ox + oy*oy + oz*oz - 9.0f;
    float disc = bq*bq - cq;
    bool  hit = disc > 0.0f;
    float sq = sqrtf(hit ? disc : 1.0f);
    float dnear = fmaxf(-bq - sq, 0.0f);
    float dfar  = fminf(-bq + sq, 100.0f);
    bool  mask_bound = hit && (dnear < dfar);

    float* scal = sscal[warp];

    // ---------------- Phase A: sample evals (2 per lane) ----------------
    unsigned vm0 = 0u, vm1 = 0u;
    float minv = 3.402823466e38f;
    int   minj = 0;
    #pragma unroll
    for (int half = 0; half < 2; ++half) {
        int s = lane + half*32;
        float t = (float)s / 63.0f;
        float dd = dnear*(1.0f - t) + dfar*t;
        float x0 = fmaf(dx, dd, ox);
        float x1 = fmaf(dy, dd, oy);
        float x2 = fmaf(dz, dd, oz);
        unsigned long long X0 = pk2(x0, x0);
        unsigned long long X1 = pk2(x1, x1);
        unsigned long long X2 = pk2(x2, x2);
        float acc0 = 0.0f, acc1 = 0.0f;
        #pragma unroll 8
        for (int p = 0; p < NPAIR; ++p) {
            ulonglong2 A  = *reinterpret_cast<const ulonglong2*>(&sPA[p]);
            ulonglong2 Bv = *reinterpret_cast<const ulonglong2*>(&sPB[p]);
            float2 m2 = sM2[p];
            unsigned long long pre2 = fma2(X0, A.x, fma2(X1, A.y, fma2(X2, Bv.x, Bv.y)));
            float p0, p1; upk2(pre2, p0, p1);
            float e0 = fast_ex2(p0);
            float e1 = fast_ex2(p1);
            float a    = 1.0f + e0;
            float prod = fmaf(a, e1, a);               // (1+e0)(1+e1)
            float sa   = fmaf(m2.x, e1, m2.x);         // m2x*(1+e1)
            float sb   = fmaf(m2.y, e0, m2.y);         // m2y*(1+e0)
            float rp   = fast_rcp(prod);
            acc0 = fmaf(sa, rp, acc0);                 // m2x/(1+e0)
            acc1 = fmaf(sb, rp, acc1);                 // m2y/(1+e1)
        }
        float acc = acc0 + acc1;
        float nrm = fast_sqrt(x0*x0 + x1*x1 + x2*x2);
        float sv = acc + cbase - nrm;
        bool valid = nrm < 3.0f;
        scal[s] = sv;
        unsigned bal = __ballot_sync(FULL, valid);
        if (half == 0) vm0 = bal; else vm1 = bal;
        if (s >= 1 && sv < minv) { minv = sv; minj = s - 1; }
    }
    __syncwarp();

    // warp-reduce argmin (first occurrence on ties -> smaller index)
    #pragma unroll
    for (int off = 16; off >= 1; off >>= 1) {
        float ov = __shfl_xor_sync(FULL, minv, off);
        int   oj = __shfl_xor_sync(FULL, minj, off);
        if (ov < minv || (ov == minv && oj < minj)) { minv = ov; minj = oj; }
    }

    // ---------------- Phase B: interval search, 8 lanes per level ----------------
    int   mylev = lane & 3;
    int   grp   = lane >> 2;
    float lval  = slev[mylev];
    float brank = -3.402823466e38f;
    int   bj    = 63;
    int   anyi  = 0;
    #pragma unroll
    for (int k = 0; k < 8; ++k) {
        int j = grp*8 + k;
        if (j < 63) {
            float sf = scal[j], sb = scal[j+1];
            float diff = lval - sb;
            float sgn = (diff > 0.0f) ? 1.0f : ((diff < 0.0f) ? -1.0f : 0.0f);
            float rank = sgn * (float)(63 - j);
            if (rank > brank) { brank = rank; bj = j; }   // ascending j -> first max kept
            unsigned wv  = (j  < 32) ? vm0 : vm1;
            unsigned wv1 = (j+1 < 32) ? vm0 : vm1;
            bool vj  = (wv  >> (j & 31)) & 1u;
            bool vj1 = (wv1 >> ((j+1) & 31)) & 1u;
            if ((sf >= lval) && (lval >= sb) && vj && vj1) anyi = 1;
        }
    }
    #pragma unroll
    for (int off = 4; off <= 16; off <<= 1) {
        float orank = __shfl_xor_sync(FULL, brank, off);
        int   obj   = __shfl_xor_sync(FULL, bj, off);
        int   oany  = __shfl_xor_sync(FULL, anyi, off);
        anyi |= oany;
        if (orank > brank || (orank == brank && obj < bj)) { brank = orank; bj = obj; }
    }
    int idxsel = anyi ? bj : minj;

    // ---------------- Phase C: secant (warp-collective evals), per level ----------------
    ulonglong2 cA  = *reinterpret_cast<const ulonglong2*>(&sPA[lane]);
    ulonglong2 cB  = *reinterpret_cast<const ulonglong2*>(&sPB[lane]);
    float2 cM2 = sM2[lane];
    float  w2pair = -0.5f * (cM2.x + cM2.y);   // w2_j + w2_j1; warp-sums to sw2sum

    float dint[LVL];
    int   mint[LVL];
    #pragma unroll
    for (int lev = 0; lev < LVL; ++lev) {
        int   idx = __shfl_sync(FULL, idxsel, lev);
        float lv  = slev[lev];
        float tF = (float)idx / 63.0f;
        float tB = (float)(idx+1) / 63.0f;
        float d_front = dnear*(1.0f - tF) + dfar*tF;
        float d_back  = dnear*(1.0f - tB) + dfar*tB;
        float s_front = scal[idx], s_back = scal[idx+1];
        bool  m_int = (s_front >= lv) && (lv >= s_back);
        float sdiff = s_front - s_back;
        bool  mvd = fabsf(sdiff) > 1e-4f;
        bool  m_sec = m_int && mvd;
        float d_sec = ((lv - s_back)*d_front + (s_front - lv)*d_back) / (mvd ? sdiff : 1.0f);
        float d_init = m_sec ? d_sec : d_back;

        float dfs = d_front, dbs = d_back, sfs = s_front, sbs = s_back, dcur = d_init;
        #pragma unroll
        for (int it = 0; it < 4; ++it) {
            float x0 = fmaf(dx, dcur, ox);
            float x1 = fmaf(dy, dcur, oy);
            float x2 = fmaf(dz, dcur, oz);
            unsigned long long X0 = pk2(x0, x0);
            unsigned long long X1 = pk2(x1, x1);
            unsigned long long X2 = pk2(x2, x2);
            unsigned long long pre2 = fma2(X0, cA.x, fma2(X1, cA.y, fma2(X2, cB.x, cB.y)));
            float p0, p1; upk2(pre2, p0, p1);
            float e0 = fast_ex2(p0);
            float e1 = fast_ex2(p1);
            float a    = 1.0f + e0;
            float prod = fmaf(a, e1, a);
            float sa   = fmaf(cM2.x, e1, cM2.x);
            float sb   = fmaf(cM2.y, e0, cM2.y);
            float rp   = fast_rcp(prod);
            float u    = sa + sb;
            float part = fmaf(u, rp, w2pair);   // m2x/(1+e0) + m2y/(1+e1) + (w2_j+w2_j1)
            #pragma unroll
            for (int off = 16; off >= 1; off >>= 1)
                part += __shfl_xor_sync(FULL, part, off);   // identical on all lanes
            float nrm = fast_sqrt(x0*x0 + x1*x1 + x2*x2);
            float s_mid = part + addc - nrm;
            bool mv = nrm < 3.0f;
            bool upf = (s_mid > lv) && mv;
            bool upb = (s_mid < lv) && mv;
            if (upf) { dfs = dcur; sfs = s_mid; }
            if (upb) { dbs = dcur; sbs = s_mid; }
            float sd = sfs - sbs;
            bool ok = fabsf(sd) > 1e-4f;
            float dn = ((lv - sbs)*dfs + (sfs - lv)*dbs) / (ok ? sd : 1.0f);
            dcur = ok ? dn : dcur;
        }
        dint[lev] = m_sec ? dcur : d_init;
        mint[lev] = m_int ? 1 : 0;
    }

    // ---------------- stable ascending sort of 4 (adjacent swaps, strict <) ----------------
    float d0 = dint[0], d1 = dint[1], d2 = dint[2], d3 = dint[3];
    int   m0 = mint[0], m1 = mint[1], m2 = mint[2], m3 = mint[3];
    #define CSW(da,ma,db,mb) do { if ((db) < (da)) { float _t=(da); (da)=(db); (db)=_t; int _m=(ma); (ma)=(mb); (mb)=_m; } } while(0)
    CSW(d0,m0,d1,m1); CSW(d1,m1,d2,m2); CSW(d2,m2,d3,m3);
    CSW(d0,m0,d1,m1); CSW(d1,m1,d2,m2);
    CSW(d0,m0,d1,m1);
    #undef CSW

    if (lane == 0) {
        float4 dv = mask_bound ? make_float4(d0, d1, d2, d3)
                               : make_float4(0.f, 0.f, 0.f, 0.f);
        *reinterpret_cast<float4*>(out + (size_t)ray*4) = dv;
        if (do_mask) {
            float4 mv4 = mask_bound ? make_float4((float)m0, (float)m1, (float)m2, (float)m3)
                                    : make_float4(0.f, 0.f, 0.f, 0.f);
            *reinterpret_cast<float4*>(out + (size_t)N*4 + (size_t)ray*4) = mv4;
        }
    }
}

extern "C" void kernel_launch(void* const* d_in, const int* in_sizes, int n_in,
                              void* d_out, int out_size) {
    const float* rays_o = (const float*)d_in[0];
    const float* rays_d = (const float*)d_in[1];
    const float* levels = (const float*)d_in[2];
    const float* W1     = (const float*)d_in[3];
    const float* b1     = (const float*)d_in[4];
    const float* W2     = (const float*)d_in[5];
    const float* b2     = (const float*)d_in[6];
    int N = in_sizes[0] / 3;
    int do_mask = (out_size >= 2 * N * LVL) ? 1 : 0;
    int blocks = (N + WPB - 1) / WPB;
    mr_kernel<<<blocks, 128>>>(rays_o, rays_d, levels, W1, b1, W2, b2,
                               (float*)d_out, N, do_mask);
}